// round 5
// baseline (speedup 1.0000x reference)
#include <cuda_runtime.h>
#include <cuda_bf16.h>

#define DD 64
#define MAXN 50176
#define MAXE 1310720

// Scratch (device globals: no allocation allowed)
__device__ __align__(16) float g_hmsg[MAXN * DD];     // 12.8 MB
__device__ __align__(16) float g_hneigh[MAXN * DD];   // 12.8 MB
__device__ float    g_s1[MAXN];
__device__ float    g_s2[MAXN];
__device__ int      g_deg[MAXN];
__device__ int      g_base[MAXN + 1];
__device__ int      g_cursor[MAXN];
__device__ int      g_dst[MAXE];
__device__ unsigned g_pk[MAXE];       // src | biasbit<<31 (edge order)
__device__ unsigned g_sorted[MAXE];   // packed, sorted by dst
__device__ float    g_e[MAXE];        // per-sorted-edge scratch
__device__ int      g_is64;

// ---------------------------------------------------------------------------
// K0: dtype probe. indices values are < 2^31 and non-negative; if the data is
// int64 (little-endian) every odd 32-bit word is 0. For int32 random indices
// the OR of 1024 odd words is ~never 0.
// ---------------------------------------------------------------------------
__global__ void k0_probe(const int* __restrict__ raw, int twoE)
{
    unsigned o = 0;
    int n = min(twoE, 2048);
    for (int i = 1; i < n; i += 2) o |= (unsigned)raw[i];
    g_is64 = (o == 0) ? 1 : 0;
}

// ---------------------------------------------------------------------------
// K1: per-node precompute.
//   h_msg[n,d] = sum_k feat[n,k]*W1[d,k] + W1_b[d]
//   s1[n] = feat[n,:] . v1 + c1   (v1 = W_att_w^T a1, c1 = W_att_b . a1)
//   s2[n] = feat[n,:] . v2 + c2 ;  deg[n] = 0
// 256 threads = 4 nodes x 64 lanes; thread d holds W1 row d in registers.
// ---------------------------------------------------------------------------
__global__ void __launch_bounds__(256) k1_node_pre(
    const float* __restrict__ feat,
    const float* __restrict__ W1w, const float* __restrict__ W1b,
    const float* __restrict__ Wattw, const float* __restrict__ Wattb,
    const float* __restrict__ a, int N)
{
    __shared__ float v1s[DD], v2s[DD];
    __shared__ float c12[2];
    __shared__ float4 fs[4][16];
    __shared__ float red1[4][64], red2[4][64];

    int t = threadIdx.x;
    int sub = t >> 6;
    int d   = t & 63;

    if (t < 64) {
        float v1 = 0.f, v2 = 0.f;
        for (int dd = 0; dd < 64; dd++) {
            float w = Wattw[dd * 64 + t];
            v1 += w * a[dd];
            v2 += w * a[64 + dd];
        }
        v1s[t] = v1; v2s[t] = v2;
    } else if (t == 64) {
        float c1 = 0.f, c2 = 0.f;
        for (int dd = 0; dd < 64; dd++) {
            float b = Wattb[dd];
            c1 += b * a[dd];
            c2 += b * a[64 + dd];
        }
        c12[0] = c1; c12[1] = c2;
    }

    float4 w[16];
#pragma unroll
    for (int j = 0; j < 16; j++)
        w[j] = reinterpret_cast<const float4*>(W1w)[d * 16 + j];
    float bd = W1b[d];

    __syncthreads();
    float c1 = c12[0], c2 = c12[1];

    int Q = (N + 3) >> 2;
    for (int q = blockIdx.x; q < Q; q += gridDim.x) {
        int n = q * 4 + sub;
        float fd = 0.f;
        if (n < N) fd = feat[n * 64 + d];
        reinterpret_cast<float*>(&fs[sub][0])[d] = fd;
        red1[sub][d] = fd * v1s[d];
        red2[sub][d] = fd * v2s[d];
        __syncthreads();

        if (d < 32) {
            float p1 = red1[sub][d] + red1[sub][d + 32];
            float p2 = red2[sub][d] + red2[sub][d + 32];
#pragma unroll
            for (int off = 16; off > 0; off >>= 1) {
                p1 += __shfl_down_sync(0xffffffffu, p1, off);
                p2 += __shfl_down_sync(0xffffffffu, p2, off);
            }
            if (d == 0 && n < N) {
                g_s1[n] = p1 + c1;
                g_s2[n] = p2 + c2;
                g_deg[n] = 0;
            }
        }

        float acc = bd;
#pragma unroll
        for (int j = 0; j < 16; j++) {
            float4 f = fs[sub][j];
            acc += f.x * w[j].x + f.y * w[j].y + f.z * w[j].z + f.w * w[j].w;
        }
        if (n < N) g_hmsg[n * 64 + d] = acc;
        __syncthreads();
    }
}

// ---------------------------------------------------------------------------
// K2: canonicalize edges (either dtype) + degree histogram. Clamped indices.
// ---------------------------------------------------------------------------
__global__ void k2_canon(const void* __restrict__ idxv,
                         const void* __restrict__ etv, int E, int N)
{
    int i = blockIdx.x * blockDim.x + threadIdx.x;
    if (i >= E) return;
    int s, d2; long long et;
    if (g_is64) {
        s  = (int)((const long long*)idxv)[i];
        d2 = (int)((const long long*)idxv)[E + i];
        et = ((const long long*)etv)[i];
    } else {
        s  = ((const int*)idxv)[i];
        d2 = ((const int*)idxv)[E + i];
        et = ((const int*)etv)[i];
    }
    s  = min(max(s, 0),  N - 1);
    d2 = min(max(d2, 0), N - 1);
    g_pk[i]  = (unsigned)s | ((et == 0) ? 0x80000000u : 0u);
    g_dst[i] = d2;
    atomicAdd(&g_deg[d2], 1);
}

// ---------------------------------------------------------------------------
// K3: exclusive scan of degrees (single block, 1024 threads)
// ---------------------------------------------------------------------------
__global__ void __launch_bounds__(1024) k3_scan(int N)
{
    __shared__ int part[1024];
    int t = threadIdx.x;
    int C = (N + 1023) >> 10;
    int start = t * C;
    int end   = min(start + C, N);
    int s = 0;
    for (int i = start; i < end; i++) s += g_deg[i];
    part[t] = s;
    __syncthreads();
    for (int off = 1; off < 1024; off <<= 1) {
        int v = (t >= off) ? part[t - off] : 0;
        __syncthreads();
        part[t] += v;
        __syncthreads();
    }
    int b = part[t] - s;
    for (int i = start; i < end; i++) {
        g_base[i]   = b;
        g_cursor[i] = b;
        b += g_deg[i];
    }
    if (t == 1023) g_base[N] = part[1023];
}

// ---------------------------------------------------------------------------
// K4: counting-sort fill (edge records grouped by dst)
// ---------------------------------------------------------------------------
__global__ void k4_fill(int E)
{
    int i = blockIdx.x * blockDim.x + threadIdx.x;
    if (i >= E) return;
    int pos = atomicAdd(&g_cursor[g_dst[i]], 1);
    g_sorted[pos] = g_pk[i];
}

// ---------------------------------------------------------------------------
// K5: warp-per-node fused softmax + gather (NO atomics).
// ---------------------------------------------------------------------------
__global__ void __launch_bounds__(256) k5_gather(int N)
{
    int warp = threadIdx.x >> 5;
    int lane = threadIdx.x & 31;
    int v = blockIdx.x * 8 + warp;
    if (v >= N) return;

    int base = g_base[v];
    int deg  = g_deg[v];
    float s2v = g_s2[v];

    float m = -1e30f;
    for (int j = lane; j < deg; j += 32) {
        unsigned p = g_sorted[base + j];
        int src = (int)(p & 0x7FFFFFFFu);
        float e = (g_s1[src] + s2v + ((p >> 31) ? 5.0f : 0.0f)) * 0.125f;
        e = (e > 0.f) ? e : 0.2f * e;
        g_e[base + j] = e;
        m = fmaxf(m, e);
    }
#pragma unroll
    for (int off = 16; off > 0; off >>= 1)
        m = fmaxf(m, __shfl_xor_sync(0xffffffffu, m, off));

    float sum = 0.f;
    for (int j = lane; j < deg; j += 32) {
        float ex = __expf(g_e[base + j] - m);
        g_e[base + j] = ex;
        sum += ex;
    }
#pragma unroll
    for (int off = 16; off > 0; off >>= 1)
        sum += __shfl_xor_sync(0xffffffffu, sum, off);
    float inv = 1.0f / (sum + 1e-9f);

    float2 acc = make_float2(0.f, 0.f);
    for (int j0 = 0; j0 < deg; j0 += 32) {
        int nj = min(32, deg - j0);
        unsigned p = 0; float ex = 0.f;
        if (lane < nj) {
            p  = g_sorted[base + j0 + lane];
            ex = g_e[base + j0 + lane];
        }
        for (int jj = 0; jj < nj; jj++) {
            int src  = __shfl_sync(0xffffffffu, (int)(p & 0x7FFFFFFFu), jj);
            float al = __shfl_sync(0xffffffffu, ex, jj) * inv;
            float2 hv = *reinterpret_cast<const float2*>(&g_hmsg[src * 64 + lane * 2]);
            acc.x += al * hv.x;
            acc.y += al * hv.y;
        }
    }
    *reinterpret_cast<float2*>(&g_hneigh[v * 64 + lane * 2]) = acc;
}

// ---------------------------------------------------------------------------
// K6: per-node output.
// ---------------------------------------------------------------------------
__global__ void __launch_bounds__(256) k6_out(
    const float* __restrict__ feat,
    const float* __restrict__ W2w, const float* __restrict__ W2b,
    float* __restrict__ out, int N)
{
    __shared__ float4 ps[4][16];
    int t = threadIdx.x;
    int sub = t >> 6, d = t & 63;

    float4 w[16];
#pragma unroll
    for (int j = 0; j < 16; j++)
        w[j] = reinterpret_cast<const float4*>(W2w)[d * 16 + j];
    float bd = W2b[d];

    int Q = (N + 3) >> 2;
    for (int q = blockIdx.x; q < Q; q += gridDim.x) {
        int n = q * 4 + sub;
        float hs = 0.f, hn = 0.f;
        if (n < N) {
            hs = feat[n * 64 + d];
            hn = g_hneigh[n * 64 + d];
        }
        reinterpret_cast<float*>(&ps[sub][0])[d] = hs * hn;
        __syncthreads();

        float acc = bd;
#pragma unroll
        for (int j = 0; j < 16; j++) {
            float4 f = ps[sub][j];
            acc += f.x * w[j].x + f.y * w[j].y + f.z * w[j].z + f.w * w[j].w;
        }
        float o = hs + hn + acc;
        o = (o > 0.f) ? o : 0.2f * o;
        if (n < N) out[n * 64 + d] = o;
        __syncthreads();
    }
}

// ---------------------------------------------------------------------------
// Launch. Inputs identified by SIZE, not position:
//   big three: indices (2E), edge_types (E), features (N*64), with
//   size(indices) == 2*size(edge_types).
//   4096-sized in relative order: W1_w, W2_w, W_att_w
//   64-sized  in relative order: W1_b, W2_b, W_att_b
//   128-sized: a.  size-1 (num_nodes scalar): skipped.
// ---------------------------------------------------------------------------
extern "C" void kernel_launch(void* const* d_in, const int* in_sizes, int n_in,
                              void* d_out, int out_size)
{
    const void  *idx = nullptr, *etype = nullptr;
    const float *feat = nullptr;
    const float *Wmat[3] = {nullptr, nullptr, nullptr};  // W1_w, W2_w, W_att_w
    const float *Wb[3]   = {nullptr, nullptr, nullptr};  // W1_b, W2_b, W_att_b
    const float *a = nullptr;
    int nm = 0, nb = 0;

    int big[8]; int nbig = 0;
    for (int i = 0; i < n_in; i++) {
        int s = in_sizes[i];
        if (s > 4096) { if (nbig < 8) big[nbig++] = i; }
        else if (s == 4096) { if (nm < 3) Wmat[nm++] = (const float*)d_in[i]; }
        else if (s == 128)  { a = (const float*)d_in[i]; }
        else if (s == 64)   { if (nb < 3) Wb[nb++] = (const float*)d_in[i]; }
        // s == 1 (num_nodes) skipped
    }
    // indices = the big one that is exactly 2x another big one; that other = edge_types
    for (int x = 0; x < nbig; x++)
        for (int y = 0; y < nbig; y++)
            if (x != y && in_sizes[big[x]] == 2 * in_sizes[big[y]]) {
                idx = d_in[big[x]]; etype = d_in[big[y]];
            }
    for (int x = 0; x < nbig; x++)
        if (d_in[big[x]] != idx && d_in[big[x]] != etype)
            feat = (const float*)d_in[big[x]];

    const float *W1w = Wmat[0], *W2w = Wmat[1], *Wattw = Wmat[2];
    const float *W1b = Wb[0],   *W2b = Wb[1],   *Wattb = Wb[2];

    int E = 0, N = 0;
    for (int x = 0; x < nbig; x++) {
        if (d_in[big[x]] == etype) E = in_sizes[big[x]];
        if ((const float*)d_in[big[x]] == feat) N = in_sizes[big[x]] / DD;
    }
    if (!idx || !etype || !feat || E <= 0 || N <= 0) return;

    int eb = (E + 255) / 256;
    k0_probe<<<1, 1>>>((const int*)idx, 2 * E);
    k1_node_pre<<<1184, 256>>>(feat, W1w, W1b, Wattw, Wattb, a, N);
    k2_canon<<<eb, 256>>>(idx, etype, E, N);
    k3_scan<<<1, 1024>>>(N);
    k4_fill<<<eb, 256>>>(E);
    k5_gather<<<(N + 7) / 8, 256>>>(N);
    k6_out<<<1184, 256>>>(feat, W2w, W2b, (float*)d_out, N);
}

// round 6
// speedup vs baseline: 1.3686x; 1.3686x over previous
#include <cuda_runtime.h>
#include <cuda_bf16.h>

#define DD 64
#define MAXN 50176
#define MAXE 1310720
#define SCAN_TILE 2048   // 256 threads * 8 elems
#define MAX_TILES 64

// Scratch (device globals: no allocation allowed)
__device__ __align__(16) float g_hmsg[MAXN * DD];     // 12.8 MB
__device__ __align__(16) float g_hneigh[MAXN * DD];   // 12.8 MB
__device__ float    g_s1[MAXN];
__device__ float    g_s2[MAXN];
__device__ __align__(16) int g_deg[MAXN + 64];        // padded for int4 reads
__device__ int      g_base[MAXN + 1];
__device__ int      g_cursor[MAXN];
__device__ int      g_dst[MAXE];
__device__ unsigned g_pk[MAXE];       // src | biasbit<<31 (edge order)
__device__ unsigned g_sorted[MAXE];   // packed, sorted by dst
__device__ float    g_e[MAXE];        // per-sorted-edge scratch
__device__ int      g_part[MAX_TILES];
__device__ int      g_partscan[MAX_TILES];
__device__ int      g_is64;

// ---------------------------------------------------------------------------
// K0: dtype probe. Node indices are < 2^31 and non-negative; if data is int64
// (little-endian) every odd 32-bit word is 0.
// ---------------------------------------------------------------------------
__global__ void k0_probe(const int* __restrict__ raw, int twoE)
{
    unsigned o = 0;
    int n = min(twoE, 2048);
    for (int i = 1; i < n; i += 2) o |= (unsigned)raw[i];
    g_is64 = (o == 0) ? 1 : 0;
}

// ---------------------------------------------------------------------------
// K1: per-node precompute: h_msg = feat@W1^T+b1; s1,s2 attention dots; deg=0.
// 256 threads = 4 nodes x 64 lanes; thread d holds W1 row d in registers.
// ---------------------------------------------------------------------------
__global__ void __launch_bounds__(256) k1_node_pre(
    const float* __restrict__ feat,
    const float* __restrict__ W1w, const float* __restrict__ W1b,
    const float* __restrict__ Wattw, const float* __restrict__ Wattb,
    const float* __restrict__ a, int N)
{
    __shared__ float v1s[DD], v2s[DD];
    __shared__ float c12[2];
    __shared__ float4 fs[4][16];
    __shared__ float red1[4][64], red2[4][64];

    int t = threadIdx.x;
    int sub = t >> 6;
    int d   = t & 63;

    if (t < 64) {
        float v1 = 0.f, v2 = 0.f;
        for (int dd = 0; dd < 64; dd++) {
            float w = Wattw[dd * 64 + t];
            v1 += w * a[dd];
            v2 += w * a[64 + dd];
        }
        v1s[t] = v1; v2s[t] = v2;
    } else if (t == 64) {
        float c1 = 0.f, c2 = 0.f;
        for (int dd = 0; dd < 64; dd++) {
            float b = Wattb[dd];
            c1 += b * a[dd];
            c2 += b * a[64 + dd];
        }
        c12[0] = c1; c12[1] = c2;
    }

    float4 w[16];
#pragma unroll
    for (int j = 0; j < 16; j++)
        w[j] = reinterpret_cast<const float4*>(W1w)[d * 16 + j];
    float bd = W1b[d];

    __syncthreads();
    float c1 = c12[0], c2 = c12[1];

    int Q = (N + 3) >> 2;
    for (int q = blockIdx.x; q < Q; q += gridDim.x) {
        int n = q * 4 + sub;
        float fd = 0.f;
        if (n < N) fd = feat[n * 64 + d];
        reinterpret_cast<float*>(&fs[sub][0])[d] = fd;
        red1[sub][d] = fd * v1s[d];
        red2[sub][d] = fd * v2s[d];
        __syncthreads();

        if (d < 32) {
            float p1 = red1[sub][d] + red1[sub][d + 32];
            float p2 = red2[sub][d] + red2[sub][d + 32];
#pragma unroll
            for (int off = 16; off > 0; off >>= 1) {
                p1 += __shfl_down_sync(0xffffffffu, p1, off);
                p2 += __shfl_down_sync(0xffffffffu, p2, off);
            }
            if (d == 0 && n < N) {
                g_s1[n] = p1 + c1;
                g_s2[n] = p2 + c2;
                g_deg[n] = 0;
            }
        }

        float acc = bd;
#pragma unroll
        for (int j = 0; j < 16; j++) {
            float4 f = fs[sub][j];
            acc += f.x * w[j].x + f.y * w[j].y + f.z * w[j].z + f.w * w[j].w;
        }
        if (n < N) g_hmsg[n * 64 + d] = acc;
        __syncthreads();
    }
}

// ---------------------------------------------------------------------------
// K2: canonicalize edges (either dtype) + degree histogram. Clamped indices.
// ---------------------------------------------------------------------------
__global__ void k2_canon(const void* __restrict__ idxv,
                         const void* __restrict__ etv, int E, int N)
{
    int i = blockIdx.x * blockDim.x + threadIdx.x;
    if (i >= E) return;
    int s, d2; long long et;
    if (g_is64) {
        s  = (int)((const long long*)idxv)[i];
        d2 = (int)((const long long*)idxv)[E + i];
        et = ((const long long*)etv)[i];
    } else {
        s  = ((const int*)idxv)[i];
        d2 = ((const int*)idxv)[E + i];
        et = ((const int*)etv)[i];
    }
    s  = min(max(s, 0),  N - 1);
    d2 = min(max(d2, 0), N - 1);
    g_pk[i]  = (unsigned)s | ((et == 0) ? 0x80000000u : 0u);
    g_dst[i] = d2;
    atomicAdd(&g_deg[d2], 1);
}

// ---------------------------------------------------------------------------
// K3a: per-tile partial sums of degrees (tile = 2048 = 256 thr x 8)
// ---------------------------------------------------------------------------
__global__ void __launch_bounds__(256) k3a_partial(int N)
{
    __shared__ int ws[8];
    int t = threadIdx.x;
    int b0 = blockIdx.x * SCAN_TILE;
    int s = 0;
#pragma unroll
    for (int k = 0; k < 8; k++) {
        int i = b0 + t + k * 256;
        if (i < N) s += g_deg[i];
    }
#pragma unroll
    for (int off = 16; off > 0; off >>= 1)
        s += __shfl_down_sync(0xffffffffu, s, off);
    if ((t & 31) == 0) ws[t >> 5] = s;
    __syncthreads();
    if (t < 8) {
        int v = ws[t];
#pragma unroll
        for (int off = 4; off > 0; off >>= 1)
            v += __shfl_down_sync(0xffu, v, off);
        if (t == 0) g_part[blockIdx.x] = v;
    }
}

// ---------------------------------------------------------------------------
// K3b: one-warp exclusive scan of tile partials; set g_base[N]=E.
// ---------------------------------------------------------------------------
__global__ void k3b_scanpart(int ntiles, int N, int E)
{
    int t = threadIdx.x;   // 64 threads
    int v = (t < ntiles) ? g_part[t] : 0;
    // inclusive scan over 64 lanes via 2 warps in shared
    __shared__ int sh[64];
    sh[t] = v;
    __syncthreads();
    for (int off = 1; off < 64; off <<= 1) {
        int u = (t >= off) ? sh[t - off] : 0;
        __syncthreads();
        sh[t] += u;
        __syncthreads();
    }
    if (t < ntiles) g_partscan[t] = sh[t] - v;  // exclusive
    if (t == 0) g_base[N] = E;
}

// ---------------------------------------------------------------------------
// K3c: per-tile fill of g_base/g_cursor. Each thread scans 8 consecutive
// degrees (int4 x2 loads), block-scan of per-thread sums, add tile offset.
// ---------------------------------------------------------------------------
__global__ void __launch_bounds__(256) k3c_fill(int N)
{
    __shared__ int warptot[8];
    int t = threadIdx.x;
    int lane = t & 31, wid = t >> 5;
    int b0 = blockIdx.x * SCAN_TILE;
    int i0 = b0 + t * 8;

    int d[8];
    // padded array: safe to read 8 past N within MAXN+64
    int4 p0 = *reinterpret_cast<const int4*>(&g_deg[i0]);
    int4 p1 = *reinterpret_cast<const int4*>(&g_deg[i0 + 4]);
    d[0]=p0.x; d[1]=p0.y; d[2]=p0.z; d[3]=p0.w;
    d[4]=p1.x; d[5]=p1.y; d[6]=p1.z; d[7]=p1.w;

    int s = 0;
#pragma unroll
    for (int k = 0; k < 8; k++) s += (i0 + k < N) ? d[k] : 0;

    // warp inclusive scan of per-thread sums
    int inc = s;
#pragma unroll
    for (int off = 1; off < 32; off <<= 1) {
        int u = __shfl_up_sync(0xffffffffu, inc, off);
        if (lane >= off) inc += u;
    }
    if (lane == 31) warptot[wid] = inc;
    __syncthreads();
    if (t < 8) {
        int v = warptot[t];
        int iv = v;
#pragma unroll
        for (int off = 1; off < 8; off <<= 1) {
            int u = __shfl_up_sync(0xffu, iv, off);
            if (t >= off) iv += u;
        }
        warptot[t] = iv - v;  // exclusive warp offset
    }
    __syncthreads();

    int b = g_partscan[blockIdx.x] + warptot[wid] + (inc - s);  // exclusive for this thread
#pragma unroll
    for (int k = 0; k < 8; k++) {
        int i = i0 + k;
        if (i < N) {
            g_base[i]   = b;
            g_cursor[i] = b;
            b += d[k];
        }
    }
}

// ---------------------------------------------------------------------------
// K4: counting-sort fill (edge records grouped by dst)
// ---------------------------------------------------------------------------
__global__ void k4_fill(int E)
{
    int i = blockIdx.x * blockDim.x + threadIdx.x;
    if (i >= E) return;
    int pos = atomicAdd(&g_cursor[g_dst[i]], 1);
    g_sorted[pos] = g_pk[i];
}

// ---------------------------------------------------------------------------
// K5: warp-per-node fused softmax + gather (NO atomics).
// Inner gather unrolled x4 for MLP.
// ---------------------------------------------------------------------------
__global__ void __launch_bounds__(256) k5_gather(int N)
{
    int warp = threadIdx.x >> 5;
    int lane = threadIdx.x & 31;
    int v = blockIdx.x * 8 + warp;
    if (v >= N) return;

    int base = g_base[v];
    int deg  = g_deg[v];
    float s2v = g_s2[v];

    float m = -1e30f;
    for (int j = lane; j < deg; j += 32) {
        unsigned p = g_sorted[base + j];
        int src = (int)(p & 0x7FFFFFFFu);
        float e = (g_s1[src] + s2v + ((p >> 31) ? 5.0f : 0.0f)) * 0.125f;
        e = (e > 0.f) ? e : 0.2f * e;
        g_e[base + j] = e;
        m = fmaxf(m, e);
    }
#pragma unroll
    for (int off = 16; off > 0; off >>= 1)
        m = fmaxf(m, __shfl_xor_sync(0xffffffffu, m, off));

    float sum = 0.f;
    for (int j = lane; j < deg; j += 32) {
        float ex = __expf(g_e[base + j] - m);
        g_e[base + j] = ex;
        sum += ex;
    }
#pragma unroll
    for (int off = 16; off > 0; off >>= 1)
        sum += __shfl_xor_sync(0xffffffffu, sum, off);
    float inv = 1.0f / (sum + 1e-9f);

    float2 acc = make_float2(0.f, 0.f);
    for (int j0 = 0; j0 < deg; j0 += 32) {
        int nj = min(32, deg - j0);
        unsigned p = 0; float ex = 0.f;
        if (lane < nj) {
            p  = g_sorted[base + j0 + lane];
            ex = g_e[base + j0 + lane];
        }
        int jj = 0;
        for (; jj + 4 <= nj; jj += 4) {
            int s0 = __shfl_sync(0xffffffffu, (int)(p & 0x7FFFFFFFu), jj);
            int s1 = __shfl_sync(0xffffffffu, (int)(p & 0x7FFFFFFFu), jj + 1);
            int s2 = __shfl_sync(0xffffffffu, (int)(p & 0x7FFFFFFFu), jj + 2);
            int s3 = __shfl_sync(0xffffffffu, (int)(p & 0x7FFFFFFFu), jj + 3);
            float a0 = __shfl_sync(0xffffffffu, ex, jj)     * inv;
            float a1 = __shfl_sync(0xffffffffu, ex, jj + 1) * inv;
            float a2 = __shfl_sync(0xffffffffu, ex, jj + 2) * inv;
            float a3 = __shfl_sync(0xffffffffu, ex, jj + 3) * inv;
            float2 h0 = *reinterpret_cast<const float2*>(&g_hmsg[s0 * 64 + lane * 2]);
            float2 h1 = *reinterpret_cast<const float2*>(&g_hmsg[s1 * 64 + lane * 2]);
            float2 h2 = *reinterpret_cast<const float2*>(&g_hmsg[s2 * 64 + lane * 2]);
            float2 h3 = *reinterpret_cast<const float2*>(&g_hmsg[s3 * 64 + lane * 2]);
            acc.x += a0 * h0.x + a1 * h1.x + a2 * h2.x + a3 * h3.x;
            acc.y += a0 * h0.y + a1 * h1.y + a2 * h2.y + a3 * h3.y;
        }
        for (; jj < nj; jj++) {
            int src  = __shfl_sync(0xffffffffu, (int)(p & 0x7FFFFFFFu), jj);
            float al = __shfl_sync(0xffffffffu, ex, jj) * inv;
            float2 hv = *reinterpret_cast<const float2*>(&g_hmsg[src * 64 + lane * 2]);
            acc.x += al * hv.x;
            acc.y += al * hv.y;
        }
    }
    *reinterpret_cast<float2*>(&g_hneigh[v * 64 + lane * 2]) = acc;
}

// ---------------------------------------------------------------------------
// K6: per-node output.
// ---------------------------------------------------------------------------
__global__ void __launch_bounds__(256) k6_out(
    const float* __restrict__ feat,
    const float* __restrict__ W2w, const float* __restrict__ W2b,
    float* __restrict__ out, int N)
{
    __shared__ float4 ps[4][16];
    int t = threadIdx.x;
    int sub = t >> 6, d = t & 63;

    float4 w[16];
#pragma unroll
    for (int j = 0; j < 16; j++)
        w[j] = reinterpret_cast<const float4*>(W2w)[d * 16 + j];
    float bd = W2b[d];

    int Q = (N + 3) >> 2;
    for (int q = blockIdx.x; q < Q; q += gridDim.x) {
        int n = q * 4 + sub;
        float hs = 0.f, hn = 0.f;
        if (n < N) {
            hs = feat[n * 64 + d];
            hn = g_hneigh[n * 64 + d];
        }
        reinterpret_cast<float*>(&ps[sub][0])[d] = hs * hn;
        __syncthreads();

        float acc = bd;
#pragma unroll
        for (int j = 0; j < 16; j++) {
            float4 f = ps[sub][j];
            acc += f.x * w[j].x + f.y * w[j].y + f.z * w[j].z + f.w * w[j].w;
        }
        float o = hs + hn + acc;
        o = (o > 0.f) ? o : 0.2f * o;
        if (n < N) out[n * 64 + d] = o;
        __syncthreads();
    }
}

// ---------------------------------------------------------------------------
// Launch. Inputs identified by SIZE (robust to scalar materialization):
//   indices: big array == 2x size of edge_types; features: remaining big one.
//   4096-sized in order: W1_w, W2_w, W_att_w ; 64-sized: W1_b, W2_b, W_att_b ;
//   128-sized: a.
// ---------------------------------------------------------------------------
extern "C" void kernel_launch(void* const* d_in, const int* in_sizes, int n_in,
                              void* d_out, int out_size)
{
    const void  *idx = nullptr, *etype = nullptr;
    const float *feat = nullptr;
    const float *Wmat[3] = {nullptr, nullptr, nullptr};
    const float *Wb[3]   = {nullptr, nullptr, nullptr};
    const float *a = nullptr;
    int nm = 0, nb = 0;

    int big[8]; int nbig = 0;
    for (int i = 0; i < n_in; i++) {
        int s = in_sizes[i];
        if (s > 4096) { if (nbig < 8) big[nbig++] = i; }
        else if (s == 4096) { if (nm < 3) Wmat[nm++] = (const float*)d_in[i]; }
        else if (s == 128)  { a = (const float*)d_in[i]; }
        else if (s == 64)   { if (nb < 3) Wb[nb++] = (const float*)d_in[i]; }
    }
    for (int x = 0; x < nbig; x++)
        for (int y = 0; y < nbig; y++)
            if (x != y && in_sizes[big[x]] == 2 * in_sizes[big[y]]) {
                idx = d_in[big[x]]; etype = d_in[big[y]];
            }
    for (int x = 0; x < nbig; x++)
        if (d_in[big[x]] != idx && d_in[big[x]] != etype)
            feat = (const float*)d_in[big[x]];

    const float *W1w = Wmat[0], *W2w = Wmat[1], *Wattw = Wmat[2];
    const float *W1b = Wb[0],   *W2b = Wb[1],   *Wattb = Wb[2];

    int E = 0, N = 0;
    for (int x = 0; x < nbig; x++) {
        if (d_in[big[x]] == etype) E = in_sizes[big[x]];
        if ((const float*)d_in[big[x]] == feat) N = in_sizes[big[x]] / DD;
    }
    if (!idx || !etype || !feat || E <= 0 || N <= 0) return;

    int eb = (E + 255) / 256;
    int ntiles = (N + SCAN_TILE - 1) / SCAN_TILE;

    k0_probe<<<1, 1>>>((const int*)idx, 2 * E);
    k1_node_pre<<<1184, 256>>>(feat, W1w, W1b, Wattw, Wattb, a, N);
    k2_canon<<<eb, 256>>>(idx, etype, E, N);
    k3a_partial<<<ntiles, 256>>>(N);
    k3b_scanpart<<<1, 64>>>(ntiles, N, E);
    k3c_fill<<<ntiles, 256>>>(N);
    k4_fill<<<eb, 256>>>(E);
    k5_gather<<<(N + 7) / 8, 256>>>(N);
    k6_out<<<1184, 256>>>(feat, W2w, W2b, (float*)d_out, N);
}